// round 11
// baseline (speedup 1.0000x reference)
#include <cuda_runtime.h>
#include <cuda_bf16.h>
#include <float.h>

#define BQ    4096
#define POOL  1024
#define DIM   768
#define TOPK  5
#define TOPC  8
#define PLEN  5
#define NOUT  ((size_t)BQ * TOPK * PLEN * DIM)   // 78,643,200

// -------- device scratch (fresh names v11) --------
__device__ float g11_qn[(size_t)BQ * DIM];
__device__ float g11_kn[(size_t)POOL * DIM];
__device__ float g11_dist[(size_t)BQ * POOL];
__device__ float g11_dq[BQ];
__device__ float g11_dk[POOL];
__device__ int   g11_cand[BQ * TOPC];
__device__ int   g11_topi[BQ * TOPK];
__device__ float g11_rowloss[BQ];

// ============================================================
__global__ __launch_bounds__(256) void norm_v11(const float* __restrict__ src,
                                                float* __restrict__ denom,
                                                int nrows) {
    int row = blockIdx.x * 256 + threadIdx.x;
    if (row >= nrows) return;
    const float* s = src + (size_t)row * DIM;
    float sum = 0.f;
    #pragma unroll 8
    for (int i = 0; i < DIM; i++) {
        float v = s[i];
        sum = __fadd_rn(sum, __fmul_rn(v, v));
    }
    denom[row] = fmaxf(sqrtf(sum), 1e-12f);
}

__global__ __launch_bounds__(256) void divide_v11(const float* __restrict__ src,
                                                  const float* __restrict__ denom,
                                                  float* __restrict__ dst,
                                                  int nelem) {
    int idx = blockIdx.x * 256 + threadIdx.x;
    if (idx >= nelem) return;
    dst[idx] = __fdiv_rn(src[idx], denom[idx / DIM]);
}

// ============================================================
// Coarse fp32 SGEMM: g11_dist = g11_qn @ g11_kn^T
// 128x128x16 tile, 8x8 microtile, 256 threads
// ============================================================
__global__ __launch_bounds__(256) void sgemm_v11() {
    __shared__ float As[128 * 16];
    __shared__ float Bs[16 * 128];
    const int tid = threadIdx.x;
    const int blockM = blockIdx.y, blockN = blockIdx.x;
    const float* A  = g11_qn + (size_t)blockM * 128 * DIM;
    const float* Bk = g11_kn + (size_t)blockN * 128 * DIM;
    const int tr = tid >> 4, tc = tid & 15;
    const int lRow = tid >> 2, lCol = tid & 3;

    float acc[8][8] = {};
    for (int kt = 0; kt < DIM; kt += 16) {
        #pragma unroll
        for (int r = 0; r < 128; r += 64) {
            float4 va = *(const float4*)(A  + (size_t)(lRow + r) * DIM + kt + lCol * 4);
            *(float4*)(As + (lRow + r) * 16 + lCol * 4) = va;
            float4 vb = *(const float4*)(Bk + (size_t)(lRow + r) * DIM + kt + lCol * 4);
            Bs[(lCol * 4 + 0) * 128 + lRow + r] = vb.x;
            Bs[(lCol * 4 + 1) * 128 + lRow + r] = vb.y;
            Bs[(lCol * 4 + 2) * 128 + lRow + r] = vb.z;
            Bs[(lCol * 4 + 3) * 128 + lRow + r] = vb.w;
        }
        __syncthreads();
        #pragma unroll
        for (int k = 0; k < 16; k++) {
            float rm[8], rn[8];
            #pragma unroll
            for (int i = 0; i < 8; i++) rm[i] = As[(tr * 8 + i) * 16 + k];
            #pragma unroll
            for (int j = 0; j < 8; j++) rn[j] = Bs[k * 128 + tc * 8 + j];
            #pragma unroll
            for (int i = 0; i < 8; i++)
                #pragma unroll
                for (int j = 0; j < 8; j++)
                    acc[i][j] += rm[i] * rn[j];
        }
        __syncthreads();
    }
    float* C = g11_dist + (size_t)(blockM * 128 + tr * 8) * POOL + blockN * 128 + tc * 8;
    #pragma unroll
    for (int i = 0; i < 8; i++) {
        *(float4*)(C + (size_t)i * POOL)     = make_float4(acc[i][0], acc[i][1], acc[i][2], acc[i][3]);
        *(float4*)(C + (size_t)i * POOL + 4) = make_float4(acc[i][4], acc[i][5], acc[i][6], acc[i][7]);
    }
}

// ============================================================
// Coarse top-8 per row (desc value, asc index). Warp per row.
// ============================================================
__global__ __launch_bounds__(256) void topk_v11() {
    const int warp = threadIdx.x >> 5;
    const int lane = threadIdx.x & 31;
    const int row  = blockIdx.x * 8 + warp;
    const float* drow = g11_dist + (size_t)row * POOL;

    float vals[32];
    #pragma unroll
    for (int j = 0; j < 32; j++) vals[j] = drow[j * 32 + lane];

    for (int it = 0; it < TOPC; it++) {
        float bv = -FLT_MAX; int bi = 0x7fffffff;
        #pragma unroll
        for (int j = 0; j < 32; j++) {
            int gi = j * 32 + lane;
            if (vals[j] > bv || (vals[j] == bv && gi < bi)) { bv = vals[j]; bi = gi; }
        }
        #pragma unroll
        for (int o = 16; o; o >>= 1) {
            float ov = __shfl_xor_sync(0xffffffffu, bv, o);
            int   oi = __shfl_xor_sync(0xffffffffu, bi, o);
            if (ov > bv || (ov == bv && oi < bi)) { bv = ov; bi = oi; }
        }
        if (lane == 0) g11_cand[row * TOPC + it] = bi;
        if ((bi & 31) == lane) {
            int jw = bi >> 5;
            #pragma unroll
            for (int j = 0; j < 32; j++) if (j == jw) vals[j] = -FLT_MAX;
        }
    }
}

// ============================================================
// Exact rescore (compensated double-float Dot2, ~fp64 accuracy)
// with CANDIDATE DEDUPLICATION: any repeated pool index among the
// 8 candidates keeps only its first occurrence; later copies are
// pushed to the bottom with -1e300 before the exact sort. This
// removes phantom duplicate entries from the top-5 (the one-slab
// mismatch) and restores sane rank5/6 boundary metadata.
// ============================================================
__device__ __forceinline__ void df_acc11(float& hi, float& lo, float p, float pe) {
    float s = hi + p;
    float bb = s - hi;
    float err = (hi - (s - bb)) + (p - bb);
    err += lo + pe;
    hi = s + err;
    lo = err - (hi - s);
}

__global__ __launch_bounds__(256) void rescore_v11() {
    const int row  = blockIdx.x;
    const int warp = threadIdx.x >> 5;
    const int lane = threadIdx.x & 31;
    const int cand = g11_cand[row * TOPC + warp];

    const float* q = g11_qn + (size_t)row  * DIM;
    const float* k = g11_kn + (size_t)cand * DIM;

    float hi = 0.f, lo = 0.f;
    #pragma unroll
    for (int j = 0; j < DIM / 32; j++) {
        float a = q[j * 32 + lane];
        float b = k[j * 32 + lane];
        float p  = a * b;
        float pe = fmaf(a, b, -p);
        df_acc11(hi, lo, p, pe);
    }
    #pragma unroll
    for (int o = 16; o; o >>= 1) {
        float ohi = __shfl_xor_sync(0xffffffffu, hi, o);
        float olo = __shfl_xor_sync(0xffffffffu, lo, o);
        df_acc11(hi, lo, ohi, olo);
    }

    __shared__ double sv[TOPC];
    __shared__ int    si[TOPC];
    if (lane == 0) { sv[warp] = (double)hi + (double)lo; si[warp] = cand; }
    __syncthreads();

    if (threadIdx.x == 0) {
        double lv[TOPC]; int li[TOPC];
        #pragma unroll
        for (int a = 0; a < TOPC; a++) { lv[a] = sv[a]; li[a] = si[a]; }

        // ---- DEDUP: keep first occurrence of each index ----
        #pragma unroll
        for (int a = 1; a < TOPC; a++) {
            #pragma unroll
            for (int b2 = 0; b2 < TOPC; b2++) {
                if (b2 < a && li[b2] == li[a]) lv[a] = -1e300;
            }
        }

        // full selection sort of 8: desc value, ties -> asc index
        #pragma unroll
        for (int a = 0; a < TOPC - 1; a++) {
            int best = a;
            #pragma unroll
            for (int b2 = 0; b2 < TOPC; b2++) {
                if (b2 <= a) continue;
                if (lv[b2] > lv[best] || (lv[b2] == lv[best] && li[b2] < li[best])) best = b2;
            }
            double tv = lv[best]; int ti = li[best];
            lv[best] = lv[a]; li[best] = li[a];
            lv[a] = tv; li[a] = ti;
        }

        float l = 0.f;
        #pragma unroll
        for (int a = 0; a < TOPK; a++) {
            g11_topi[row * TOPK + a] = li[a];
            l += fabsf((float)lv[a]);
        }
        g11_rowloss[row] = l;
    }
}

// ============================================================
// Gather: out[b,k,:,:] = prompt_values[top_i[b,k],:,:]
// ============================================================
__global__ __launch_bounds__(256) void gather_v11(const float* __restrict__ pv,
                                                  float* __restrict__ out) {
    const int bk = blockIdx.x;
    const int idx = g11_topi[bk];
    const float4* src = (const float4*)(pv  + (size_t)idx * PLEN * DIM);
    float4*       dst = (float4*)      (out + (size_t)bk  * PLEN * DIM);
    const int n4 = PLEN * DIM / 4;               // 960
    for (int i = threadIdx.x; i < n4; i += 256) dst[i] = src[i];
}

// ============================================================
__global__ __launch_bounds__(1024) void loss_v11(float* __restrict__ out) {
    __shared__ float red[32];
    float s = 0.f;
    for (int i = threadIdx.x; i < BQ; i += 1024) s += g11_rowloss[i];
    #pragma unroll
    for (int o = 16; o; o >>= 1) s += __shfl_xor_sync(0xffffffffu, s, o);
    if ((threadIdx.x & 31) == 0) red[threadIdx.x >> 5] = s;
    __syncthreads();
    if (threadIdx.x < 32) {
        float v = red[threadIdx.x];
        #pragma unroll
        for (int o = 16; o; o >>= 1) v += __shfl_xor_sync(0xffffffffu, v, o);
        if (threadIdx.x == 0) out[0] = v / (float)BQ;
    }
}

// ============================================================
extern "C" void kernel_launch(void* const* d_in, const int* in_sizes, int n_in,
                              void* d_out, int out_size) {
    const float* query = (const float*)d_in[0];   // [4096, 768]
    const float* pkeys = (const float*)d_in[1];   // [1024, 768]
    const float* pvals = (const float*)d_in[2];   // [1024, 5, 768]
    float* out = (float*)d_out;

    float *qn_ptr, *kn_ptr, *dq_ptr, *dk_ptr;
    cudaGetSymbolAddress((void**)&qn_ptr, g11_qn);
    cudaGetSymbolAddress((void**)&kn_ptr, g11_kn);
    cudaGetSymbolAddress((void**)&dq_ptr, g11_dq);
    cudaGetSymbolAddress((void**)&dk_ptr, g11_dk);

    norm_v11<<<(POOL + 255) / 256, 256>>>(pkeys, dk_ptr, POOL);
    norm_v11<<<(BQ   + 255) / 256, 256>>>(query, dq_ptr, BQ);
    divide_v11<<<(POOL * DIM + 255) / 256, 256>>>(pkeys, dk_ptr, kn_ptr, POOL * DIM);
    divide_v11<<<(BQ   * DIM + 255) / 256, 256>>>(query, dq_ptr, qn_ptr, BQ * DIM);

    dim3 gemm_grid(POOL / 128, BQ / 128);   // (8, 32)
    sgemm_v11<<<gemm_grid, 256>>>();

    topk_v11<<<BQ / 8, 256>>>();

    rescore_v11<<<BQ, 256>>>();

    gather_v11<<<BQ * TOPK, 256>>>(pvals, out);

    if ((size_t)out_size > NOUT)
        loss_v11<<<1, 1024>>>(out + NOUT);
}

// round 13
// speedup vs baseline: 1.8133x; 1.8133x over previous
#include <cuda_runtime.h>
#include <cuda_bf16.h>
#include <mma.h>
#include <float.h>

using namespace nvcuda;

#define BQ    4096
#define POOL  1024
#define DIM   768
#define TOPK  5
#define TOPC  8
#define PLEN  5
#define NOUT  ((size_t)BQ * TOPK * PLEN * DIM)   // 78,643,200

// -------- device scratch (v13) --------
__device__ float g13_qn[(size_t)BQ * DIM];
__device__ float g13_kn[(size_t)POOL * DIM];
__device__ float g13_dist[(size_t)BQ * POOL];
__device__ float g13_dq[BQ];
__device__ float g13_dk[POOL];
__device__ int   g13_cand[BQ * TOPC];
__device__ int   g13_topi[BQ * TOPK];
__device__ float g13_rowloss[BQ];

// ============================================================
// Coalesced norm with BITWISE-IDENTICAL semantics to v11's
// sequential fp32 sum: per row, sum = fadd(sum, fmul(v,v)) in
// ascending i order. 32 rows per block; smem-transposed tiles
// make the global loads coalesced; thread r owns row r's chain.
// ============================================================
__global__ __launch_bounds__(256) void norm_v13(const float* __restrict__ src,
                                                float* __restrict__ denom) {
    __shared__ float tile[32][33];
    const int rowBase = blockIdx.x * 32;
    const int tid = threadIdx.x;
    float sum = 0.f;
    for (int c0 = 0; c0 < DIM; c0 += 32) {
        #pragma unroll
        for (int e = tid; e < 1024; e += 256) {
            int r = e >> 5, c = e & 31;
            tile[r][c] = src[(size_t)(rowBase + r) * DIM + c0 + c];
        }
        __syncthreads();
        if (tid < 32) {
            #pragma unroll
            for (int j = 0; j < 32; j++) {
                float v = tile[tid][j];
                sum = __fadd_rn(sum, __fmul_rn(v, v));   // exact v11 order
            }
        }
        __syncthreads();
    }
    if (tid < 32) denom[rowBase + tid] = fmaxf(sqrtf(sum), 1e-12f);
}

// Element-wise divide — verbatim v11 arithmetic.
__global__ __launch_bounds__(256) void divide_v13(const float* __restrict__ src,
                                                  const float* __restrict__ denom,
                                                  float* __restrict__ dst,
                                                  int nelem) {
    int idx = blockIdx.x * 256 + threadIdx.x;
    if (idx >= nelem) return;
    dst[idx] = __fdiv_rn(src[idx], denom[idx / DIM]);
}

// ============================================================
// Coarse tf32 tensor-core GEMM: g13_dist = qn @ kn^T, fp32 accum.
// Block 128(M)x64(N), 8 warps (4x2), 32x32 per warp, K chunk 32.
// tf32 noise ~1e-5 — only membership of true top-5 in coarse
// top-8 matters (margins ~1e-2); the exact rescore fixes order.
// ============================================================
#define LDA 36   // 32 + 4 pad floats (144B rows, 16B-aligned)

__global__ __launch_bounds__(256) void gemm_tf32_v13() {
    __shared__ float As[128 * LDA];
    __shared__ float Bs[64 * LDA];
    const int tid = threadIdx.x;
    const int wid = tid >> 5;
    const int wm  = wid & 3, wn = wid >> 2;
    const float* Ag = g13_qn + (size_t)blockIdx.y * 128 * DIM;
    const float* Bg = g13_kn + (size_t)blockIdx.x * 64  * DIM;

    wmma::fragment<wmma::accumulator, 16, 16, 8, float> c[2][2];
    #pragma unroll
    for (int i = 0; i < 2; i++)
        #pragma unroll
        for (int j = 0; j < 2; j++) wmma::fill_fragment(c[i][j], 0.0f);

    for (int kt = 0; kt < DIM; kt += 32) {
        __syncthreads();
        #pragma unroll
        for (int ch = 0; ch < 4; ch++) {          // A: 128x32 = 1024 float4
            int chunk = tid + ch * 256;
            int row = chunk >> 3, c4 = chunk & 7;
            *(float4*)(As + row * LDA + c4 * 4) =
                *(const float4*)(Ag + (size_t)row * DIM + kt + c4 * 4);
        }
        #pragma unroll
        for (int ch = 0; ch < 2; ch++) {          // B: 64x32 = 512 float4
            int chunk = tid + ch * 256;
            int row = chunk >> 3, c4 = chunk & 7;
            *(float4*)(Bs + row * LDA + c4 * 4) =
                *(const float4*)(Bg + (size_t)row * DIM + kt + c4 * 4);
        }
        __syncthreads();

        #pragma unroll
        for (int ks = 0; ks < 32; ks += 8) {
            wmma::fragment<wmma::matrix_a, 16, 16, 8, wmma::precision::tf32, wmma::row_major> a[2];
            wmma::fragment<wmma::matrix_b, 16, 16, 8, wmma::precision::tf32, wmma::col_major> b[2];
            #pragma unroll
            for (int i = 0; i < 2; i++) {
                wmma::load_matrix_sync(a[i], As + (wm * 32 + i * 16) * LDA + ks, LDA);
                #pragma unroll
                for (int t = 0; t < a[i].num_elements; t++)
                    a[i].x[t] = wmma::__float_to_tf32(a[i].x[t]);
            }
            #pragma unroll
            for (int j = 0; j < 2; j++) {
                wmma::load_matrix_sync(b[j], Bs + (wn * 32 + j * 16) * LDA + ks, LDA);
                #pragma unroll
                for (int t = 0; t < b[j].num_elements; t++)
                    b[j].x[t] = wmma::__float_to_tf32(b[j].x[t]);
            }
            #pragma unroll
            for (int i = 0; i < 2; i++)
                #pragma unroll
                for (int j = 0; j < 2; j++)
                    wmma::mma_sync(c[i][j], a[i], b[j], c[i][j]);
        }
    }

    #pragma unroll
    for (int i = 0; i < 2; i++)
        #pragma unroll
        for (int j = 0; j < 2; j++) {
            int row0 = blockIdx.y * 128 + wm * 32 + i * 16;
            int col0 = blockIdx.x * 64  + wn * 32 + j * 16;
            wmma::store_matrix_sync(g13_dist + (size_t)row0 * POOL + col0,
                                    c[i][j], POOL, wmma::mem_row_major);
        }
}

// ============================================================
// Coarse top-8 per row — verbatim v11. Warp per row.
// ============================================================
__global__ __launch_bounds__(256) void topk_v13() {
    const int warp = threadIdx.x >> 5;
    const int lane = threadIdx.x & 31;
    const int row  = blockIdx.x * 8 + warp;
    const float* drow = g13_dist + (size_t)row * POOL;

    float vals[32];
    #pragma unroll
    for (int j = 0; j < 32; j++) vals[j] = drow[j * 32 + lane];

    for (int it = 0; it < TOPC; it++) {
        float bv = -FLT_MAX; int bi = 0x7fffffff;
        #pragma unroll
        for (int j = 0; j < 32; j++) {
            int gi = j * 32 + lane;
            if (vals[j] > bv || (vals[j] == bv && gi < bi)) { bv = vals[j]; bi = gi; }
        }
        #pragma unroll
        for (int o = 16; o; o >>= 1) {
            float ov = __shfl_xor_sync(0xffffffffu, bv, o);
            int   oi = __shfl_xor_sync(0xffffffffu, bi, o);
            if (ov > bv || (ov == bv && oi < bi)) { bv = ov; bi = oi; }
        }
        if (lane == 0) g13_cand[row * TOPC + it] = bi;
        if ((bi & 31) == lane) {
            int jw = bi >> 5;
            #pragma unroll
            for (int j = 0; j < 32; j++) if (j == jw) vals[j] = -FLT_MAX;
        }
    }
}

// ============================================================
// Exact rescore + dedup — verbatim v11 (the passing version).
// ============================================================
__device__ __forceinline__ void df_acc13(float& hi, float& lo, float p, float pe) {
    float s = hi + p;
    float bb = s - hi;
    float err = (hi - (s - bb)) + (p - bb);
    err += lo + pe;
    hi = s + err;
    lo = err - (hi - s);
}

__global__ __launch_bounds__(256) void rescore_v13() {
    const int row  = blockIdx.x;
    const int warp = threadIdx.x >> 5;
    const int lane = threadIdx.x & 31;
    const int cand = g13_cand[row * TOPC + warp];

    const float* q = g13_qn + (size_t)row  * DIM;
    const float* k = g13_kn + (size_t)cand * DIM;

    float hi = 0.f, lo = 0.f;
    #pragma unroll
    for (int j = 0; j < DIM / 32; j++) {
        float a = q[j * 32 + lane];
        float b = k[j * 32 + lane];
        float p  = a * b;
        float pe = fmaf(a, b, -p);
        df_acc13(hi, lo, p, pe);
    }
    #pragma unroll
    for (int o = 16; o; o >>= 1) {
        float ohi = __shfl_xor_sync(0xffffffffu, hi, o);
        float olo = __shfl_xor_sync(0xffffffffu, lo, o);
        df_acc13(hi, lo, ohi, olo);
    }

    __shared__ double sv[TOPC];
    __shared__ int    si[TOPC];
    if (lane == 0) { sv[warp] = (double)hi + (double)lo; si[warp] = cand; }
    __syncthreads();

    if (threadIdx.x == 0) {
        double lv[TOPC]; int li[TOPC];
        #pragma unroll
        for (int a = 0; a < TOPC; a++) { lv[a] = sv[a]; li[a] = si[a]; }

        // dedup: keep first occurrence of each index
        #pragma unroll
        for (int a = 1; a < TOPC; a++) {
            #pragma unroll
            for (int b2 = 0; b2 < TOPC; b2++) {
                if (b2 < a && li[b2] == li[a]) lv[a] = -1e300;
            }
        }

        // full selection sort of 8: desc value, ties -> asc index
        #pragma unroll
        for (int a = 0; a < TOPC - 1; a++) {
            int best = a;
            #pragma unroll
            for (int b2 = 0; b2 < TOPC; b2++) {
                if (b2 <= a) continue;
                if (lv[b2] > lv[best] || (lv[b2] == lv[best] && li[b2] < li[best])) best = b2;
            }
            double tv = lv[best]; int ti = li[best];
            lv[best] = lv[a]; li[best] = li[a];
            lv[a] = tv; li[a] = ti;
        }

        float l = 0.f;
        #pragma unroll
        for (int a = 0; a < TOPK; a++) {
            g13_topi[row * TOPK + a] = li[a];
            l += fabsf((float)lv[a]);
        }
        g13_rowloss[row] = l;
    }
}

// ============================================================
// Gather — verbatim v11.
// ============================================================
__global__ __launch_bounds__(256) void gather_v13(const float* __restrict__ pv,
                                                  float* __restrict__ out) {
    const int bk = blockIdx.x;
    const int idx = g13_topi[bk];
    const float4* src = (const float4*)(pv  + (size_t)idx * PLEN * DIM);
    float4*       dst = (float4*)      (out + (size_t)bk  * PLEN * DIM);
    const int n4 = PLEN * DIM / 4;               // 960
    for (int i = threadIdx.x; i < n4; i += 256) dst[i] = src[i];
}

// ============================================================
__global__ __launch_bounds__(1024) void loss_v13(float* __restrict__ out) {
    __shared__ float red[32];
    float s = 0.f;
    for (int i = threadIdx.x; i < BQ; i += 1024) s += g13_rowloss[i];
    #pragma unroll
    for (int o = 16; o; o >>= 1) s += __shfl_xor_sync(0xffffffffu, s, o);
    if ((threadIdx.x & 31) == 0) red[threadIdx.x >> 5] = s;
    __syncthreads();
    if (threadIdx.x < 32) {
        float v = red[threadIdx.x];
        #pragma unroll
        for (int o = 16; o; o >>= 1) v += __shfl_xor_sync(0xffffffffu, v, o);
        if (threadIdx.x == 0) out[0] = v / (float)BQ;
    }
}

// ============================================================
extern "C" void kernel_launch(void* const* d_in, const int* in_sizes, int n_in,
                              void* d_out, int out_size) {
    const float* query = (const float*)d_in[0];   // [4096, 768]
    const float* pkeys = (const float*)d_in[1];   // [1024, 768]
    const float* pvals = (const float*)d_in[2];   // [1024, 5, 768]
    float* out = (float*)d_out;

    float *qn_ptr, *kn_ptr, *dq_ptr, *dk_ptr;
    cudaGetSymbolAddress((void**)&qn_ptr, g13_qn);
    cudaGetSymbolAddress((void**)&kn_ptr, g13_kn);
    cudaGetSymbolAddress((void**)&dq_ptr, g13_dq);
    cudaGetSymbolAddress((void**)&dk_ptr, g13_dk);

    norm_v13<<<POOL / 32, 256>>>(pkeys, dk_ptr);
    norm_v13<<<BQ   / 32, 256>>>(query, dq_ptr);
    divide_v13<<<(POOL * DIM + 255) / 256, 256>>>(pkeys, dk_ptr, kn_ptr, POOL * DIM);
    divide_v13<<<(BQ   * DIM + 255) / 256, 256>>>(query, dq_ptr, qn_ptr, BQ * DIM);

    dim3 gemm_grid(POOL / 64, BQ / 128);   // (16, 32)
    gemm_tf32_v13<<<gemm_grid, 256>>>();

    topk_v13<<<BQ / 8, 256>>>();

    rescore_v13<<<BQ, 256>>>();

    gather_v13<<<BQ * TOPK, 256>>>(pvals, out);

    if ((size_t)out_size > NOUT)
        loss_v13<<<1, 1024>>>(out + NOUT);
}

// round 15
// speedup vs baseline: 1.9247x; 1.0614x over previous
#include <cuda_runtime.h>
#include <cuda_bf16.h>
#include <mma.h>
#include <float.h>
#include <cstdint>

using namespace nvcuda;

#define BQ    4096
#define POOL  1024
#define DIM   768
#define TOPK  5
#define TOPC  8
#define PLEN  5
#define NOUT  ((size_t)BQ * TOPK * PLEN * DIM)   // 78,643,200

// -------- device scratch (v15) --------
__device__ float g15_qn[(size_t)BQ * DIM];
__device__ float g15_kn[(size_t)POOL * DIM];
__device__ float g15_dist[(size_t)BQ * POOL];
__device__ float g15_dq[BQ];
__device__ float g15_dk[POOL];
__device__ int   g15_cand[BQ * TOPC];
__device__ int   g15_topi[BQ * TOPK];
__device__ float g15_rowloss[BQ];

// ============================================================
// Norm — verbatim v13 (bitwise v11 semantics: sequential fp32
// fadd(fmul) chain per row, coalesced via smem transpose).
// ============================================================
__global__ __launch_bounds__(256) void norm_v15(const float* __restrict__ src,
                                                float* __restrict__ denom) {
    __shared__ float tile[32][33];
    const int rowBase = blockIdx.x * 32;
    const int tid = threadIdx.x;
    float sum = 0.f;
    for (int c0 = 0; c0 < DIM; c0 += 32) {
        #pragma unroll
        for (int e = tid; e < 1024; e += 256) {
            int r = e >> 5, c = e & 31;
            tile[r][c] = src[(size_t)(rowBase + r) * DIM + c0 + c];
        }
        __syncthreads();
        if (tid < 32) {
            #pragma unroll
            for (int j = 0; j < 32; j++) {
                float v = tile[tid][j];
                sum = __fadd_rn(sum, __fmul_rn(v, v));
            }
        }
        __syncthreads();
    }
    if (tid < 32) denom[rowBase + tid] = fmaxf(sqrtf(sum), 1e-12f);
}

// Divide — verbatim v13.
__global__ __launch_bounds__(256) void divide_v15(const float* __restrict__ src,
                                                  const float* __restrict__ denom,
                                                  float* __restrict__ dst,
                                                  int nelem) {
    int idx = blockIdx.x * 256 + threadIdx.x;
    if (idx >= nelem) return;
    dst[idx] = __fdiv_rn(src[idx], denom[idx / DIM]);
}

// ============================================================
// Coarse tf32 GEMM v15: 128(M)x128(N) block tile, K-chunk 16,
// 2-stage cp.async double buffer. 8 warps (2x4), 64x32 per warp.
// Coarse-only output -> accumulation order free.
// ============================================================
#define LDS15 20   // 16 + 4 pad floats (80B rows, 16B-aligned)

__device__ __forceinline__ void cpa16_v15(unsigned int dst, const float* src) {
    asm volatile("cp.async.ca.shared.global [%0], [%1], 16;" :: "r"(dst), "l"(src));
}

__global__ __launch_bounds__(256) void gemm_tf32_v15() {
    __shared__ float As[2][128 * LDS15];
    __shared__ float Bs[2][128 * LDS15];

    const int tid = threadIdx.x;
    const int wid = tid >> 5;
    const int wm  = wid & 1;          // 0..1 -> 64 M-rows each
    const int wn  = wid >> 1;         // 0..3 -> 32 N-cols each
    const float* Ag = g15_qn + (size_t)blockIdx.y * 128 * DIM;
    const float* Bg = g15_kn + (size_t)blockIdx.x * 128 * DIM;

    // loader coords: 512 float4 per matrix per stage, 2 per thread
    const int lr = tid >> 2;          // 0..63 base row
    const int lc = tid & 3;           // 0..3  float4 col

    wmma::fragment<wmma::accumulator, 16, 16, 8, float> c[4][2];
    #pragma unroll
    for (int i = 0; i < 4; i++)
        #pragma unroll
        for (int j = 0; j < 2; j++) wmma::fill_fragment(c[i][j], 0.0f);

    auto load_stage = [&](int s, int kt) {
        #pragma unroll
        for (int h = 0; h < 2; h++) {
            int row = lr + h * 64;
            unsigned int da = (unsigned int)__cvta_generic_to_shared(&As[s][row * LDS15 + lc * 4]);
            cpa16_v15(da, Ag + (size_t)row * DIM + kt + lc * 4);
            unsigned int db = (unsigned int)__cvta_generic_to_shared(&Bs[s][row * LDS15 + lc * 4]);
            cpa16_v15(db, Bg + (size_t)row * DIM + kt + lc * 4);
        }
        asm volatile("cp.async.commit_group;");
    };

    load_stage(0, 0);

    const int NIT = DIM / 16;   // 48
    for (int it = 0; it < NIT; it++) {
        const int cur = it & 1;
        if (it + 1 < NIT) load_stage((it + 1) & 1, (it + 1) * 16);

        if (it + 1 < NIT) asm volatile("cp.async.wait_group 1;");
        else              asm volatile("cp.async.wait_group 0;");
        __syncthreads();

        #pragma unroll
        for (int ks = 0; ks < 16; ks += 8) {
            wmma::fragment<wmma::matrix_a, 16, 16, 8, wmma::precision::tf32, wmma::row_major> a[4];
            wmma::fragment<wmma::matrix_b, 16, 16, 8, wmma::precision::tf32, wmma::col_major> b[2];
            #pragma unroll
            for (int i = 0; i < 4; i++) {
                wmma::load_matrix_sync(a[i], &As[cur][(wm * 64 + i * 16) * LDS15 + ks], LDS15);
                #pragma unroll
                for (int t = 0; t < a[i].num_elements; t++)
                    a[i].x[t] = wmma::__float_to_tf32(a[i].x[t]);
            }
            #pragma unroll
            for (int j = 0; j < 2; j++) {
                wmma::load_matrix_sync(b[j], &Bs[cur][(wn * 32 + j * 16) * LDS15 + ks], LDS15);
                #pragma unroll
                for (int t = 0; t < b[j].num_elements; t++)
                    b[j].x[t] = wmma::__float_to_tf32(b[j].x[t]);
            }
            #pragma unroll
            for (int i = 0; i < 4; i++)
                #pragma unroll
                for (int j = 0; j < 2; j++)
                    wmma::mma_sync(c[i][j], a[i], b[j], c[i][j]);
        }
        __syncthreads();
    }

    #pragma unroll
    for (int i = 0; i < 4; i++)
        #pragma unroll
        for (int j = 0; j < 2; j++) {
            int row0 = blockIdx.y * 128 + wm * 64 + i * 16;
            int col0 = blockIdx.x * 128 + wn * 32 + j * 16;
            wmma::store_matrix_sync(g15_dist + (size_t)row0 * POOL + col0,
                                    c[i][j], POOL, wmma::mem_row_major);
        }
}

// ============================================================
// Coarse top-8 per row — verbatim v13. Warp per row.
// ============================================================
__global__ __launch_bounds__(256) void topk_v15() {
    const int warp = threadIdx.x >> 5;
    const int lane = threadIdx.x & 31;
    const int row  = blockIdx.x * 8 + warp;
    const float* drow = g15_dist + (size_t)row * POOL;

    float vals[32];
    #pragma unroll
    for (int j = 0; j < 32; j++) vals[j] = drow[j * 32 + lane];

    for (int it = 0; it < TOPC; it++) {
        float bv = -FLT_MAX; int bi = 0x7fffffff;
        #pragma unroll
        for (int j = 0; j < 32; j++) {
            int gi = j * 32 + lane;
            if (vals[j] > bv || (vals[j] == bv && gi < bi)) { bv = vals[j]; bi = gi; }
        }
        #pragma unroll
        for (int o = 16; o; o >>= 1) {
            float ov = __shfl_xor_sync(0xffffffffu, bv, o);
            int   oi = __shfl_xor_sync(0xffffffffu, bi, o);
            if (ov > bv || (ov == bv && oi < bi)) { bv = ov; bi = oi; }
        }
        if (lane == 0) g15_cand[row * TOPC + it] = bi;
        if ((bi & 31) == lane) {
            int jw = bi >> 5;
            #pragma unroll
            for (int j = 0; j < 32; j++) if (j == jw) vals[j] = -FLT_MAX;
        }
    }
}

// ============================================================
// Exact rescore + dedup — v13 arithmetic, q staged in smem once.
// ============================================================
__device__ __forceinline__ void df_acc15(float& hi, float& lo, float p, float pe) {
    float s = hi + p;
    float bb = s - hi;
    float err = (hi - (s - bb)) + (p - bb);
    err += lo + pe;
    hi = s + err;
    lo = err - (hi - s);
}

__global__ __launch_bounds__(256) void rescore_v15() {
    const int row  = blockIdx.x;
    const int warp = threadIdx.x >> 5;
    const int lane = threadIdx.x & 31;
    const int cand = g15_cand[row * TOPC + warp];

    __shared__ float qs[DIM];
    for (int i = threadIdx.x; i < DIM; i += 256) qs[i] = g15_qn[(size_t)row * DIM + i];
    __syncthreads();

    const float* k = g15_kn + (size_t)cand * DIM;

    float hi = 0.f, lo = 0.f;
    #pragma unroll
    for (int j = 0; j < DIM / 32; j++) {
        float a = qs[j * 32 + lane];
        float b = k[j * 32 + lane];
        float p  = a * b;
        float pe = fmaf(a, b, -p);
        df_acc15(hi, lo, p, pe);
    }
    #pragma unroll
    for (int o = 16; o; o >>= 1) {
        float ohi = __shfl_xor_sync(0xffffffffu, hi, o);
        float olo = __shfl_xor_sync(0xffffffffu, lo, o);
        df_acc15(hi, lo, ohi, olo);
    }

    __shared__ double sv[TOPC];
    __shared__ int    si[TOPC];
    if (lane == 0) { sv[warp] = (double)hi + (double)lo; si[warp] = cand; }
    __syncthreads();

    if (threadIdx.x == 0) {
        double lv[TOPC]; int li[TOPC];
        #pragma unroll
        for (int a = 0; a < TOPC; a++) { lv[a] = sv[a]; li[a] = si[a]; }

        // dedup: keep first occurrence of each index
        #pragma unroll
        for (int a = 1; a < TOPC; a++) {
            #pragma unroll
            for (int b2 = 0; b2 < TOPC; b2++) {
                if (b2 < a && li[b2] == li[a]) lv[a] = -1e300;
            }
        }

        // full selection sort of 8: desc value, ties -> asc index
        #pragma unroll
        for (int a = 0; a < TOPC - 1; a++) {
            int best = a;
            #pragma unroll
            for (int b2 = 0; b2 < TOPC; b2++) {
                if (b2 <= a) continue;
                if (lv[b2] > lv[best] || (lv[b2] == lv[best] && li[b2] < li[best])) best = b2;
            }
            double tv = lv[best]; int ti = li[best];
            lv[best] = lv[a]; li[best] = li[a];
            lv[a] = tv; li[a] = ti;
        }

        float l = 0.f;
        #pragma unroll
        for (int a = 0; a < TOPK; a++) {
            g15_topi[row * TOPK + a] = li[a];
            l += fabsf((float)lv[a]);
        }
        g15_rowloss[row] = l;
    }
}

// ============================================================
// Gather — verbatim v13.
// ============================================================
__global__ __launch_bounds__(256) void gather_v15(const float* __restrict__ pv,
                                                  float* __restrict__ out) {
    const int bk = blockIdx.x;
    const int idx = g15_topi[bk];
    const float4* src = (const float4*)(pv  + (size_t)idx * PLEN * DIM);
    float4*       dst = (float4*)      (out + (size_t)bk  * PLEN * DIM);
    const int n4 = PLEN * DIM / 4;               // 960
    for (int i = threadIdx.x; i < n4; i += 256) dst[i] = src[i];
}

// ============================================================
__global__ __launch_bounds__(1024) void loss_v15(float* __restrict__ out) {
    __shared__ float red[32];
    float s = 0.f;
    for (int i = threadIdx.x; i < BQ; i += 1024) s += g15_rowloss[i];
    #pragma unroll
    for (int o = 16; o; o >>= 1) s += __shfl_xor_sync(0xffffffffu, s, o);
    if ((threadIdx.x & 31) == 0) red[threadIdx.x >> 5] = s;
    __syncthreads();
    if (threadIdx.x < 32) {
        float v = red[threadIdx.x];
        #pragma unroll
        for (int o = 16; o; o >>= 1) v += __shfl_xor_sync(0xffffffffu, v, o);
        if (threadIdx.x == 0) out[0] = v / (float)BQ;
    }
}

// ============================================================
extern "C" void kernel_launch(void* const* d_in, const int* in_sizes, int n_in,
                              void* d_out, int out_size) {
    const float* query = (const float*)d_in[0];   // [4096, 768]
    const float* pkeys = (const float*)d_in[1];   // [1024, 768]
    const float* pvals = (const float*)d_in[2];   // [1024, 5, 768]
    float* out = (float*)d_out;

    float *qn_ptr, *kn_ptr, *dq_ptr, *dk_ptr;
    cudaGetSymbolAddress((void**)&qn_ptr, g15_qn);
    cudaGetSymbolAddress((void**)&kn_ptr, g15_kn);
    cudaGetSymbolAddress((void**)&dq_ptr, g15_dq);
    cudaGetSymbolAddress((void**)&dk_ptr, g15_dk);

    norm_v15<<<POOL / 32, 256>>>(pkeys, dk_ptr);
    norm_v15<<<BQ   / 32, 256>>>(query, dq_ptr);
    divide_v15<<<(POOL * DIM + 255) / 256, 256>>>(pkeys, dk_ptr, kn_ptr, POOL * DIM);
    divide_v15<<<(BQ   * DIM + 255) / 256, 256>>>(query, dq_ptr, qn_ptr, BQ * DIM);

    dim3 gemm_grid(POOL / 128, BQ / 128);   // (8, 32)
    gemm_tf32_v15<<<gemm_grid, 256>>>();

    topk_v15<<<BQ / 8, 256>>>();

    rescore_v15<<<BQ, 256>>>();

    gather_v15<<<BQ * TOPK, 256>>>(pvals, out);

    if ((size_t)out_size > NOUT)
        loss_v15<<<1, 1024>>>(out + NOUT);
}